// round 2
// baseline (speedup 1.0000x reference)
#include <cuda_runtime.h>
#include <cuda_bf16.h>
#include <cstdint>
#include <cstddef>

// Problem constants
#define BT   2048
#define Hh   1280
#define Ee   896
#define NEXP 64
#define TOPK 6
#define FFN  1792
#define TOT  (BT*TOPK)   // 12288 assignments

// ---------------- device scratch (no cudaMalloc allowed) ----------------
__device__ float g_Wg[(size_t)NEXP*Hh*Ee];   // [n][h][e] repacked gate
__device__ float g_Wu[(size_t)NEXP*Hh*Ee];   // [n][h][e] repacked up
__device__ float g_Wd[(size_t)NEXP*Ee*Hh];   // [n][e][h] repacked down
__device__ float g_logits[BT*NEXP];
__device__ int   g_topi[TOT];
__device__ float g_topw[TOT];
__device__ int   g_cnt[NEXP];
__device__ int   g_off[NEXP];
__device__ int   g_list[TOT];                // token index per assignment slot (expert-grouped, stable order)
__device__ float g_lw[TOT];                  // routing weight per slot
__device__ float g_act[(size_t)TOT*Ee];      // silu(gate)*up per slot
__device__ float g_sh[(size_t)BT*FFN];       // shared silu(g)*u

// ---------------- small kernels ----------------
__global__ void zero_cnt() { if (threadIdx.x < NEXP) g_cnt[threadIdx.x] = 0; }

__global__ void scan_off() {
    if (threadIdx.x == 0) {
        int a = 0;
        for (int n = 0; n < NEXP; n++) { g_off[n] = a; a += g_cnt[n]; }
    }
}

// top-6 of logits, softmax over the 6 (== renormalized top-k of full softmax)
__global__ void router_topk() {
    int t = blockIdx.x;
    int lane = threadIdx.x;
    const float NEG = __int_as_float(0xff800000);
    float v0 = g_logits[t*NEXP + lane];
    float v1 = g_logits[t*NEXP + 32 + lane];
    int i0 = lane, i1 = lane + 32;
    float bv[TOPK]; int bi[TOPK];
    for (int k = 0; k < TOPK; k++) {
        float mv; int mi;
        if (v0 > v1 || (v0 == v1 && i0 < i1)) { mv = v0; mi = i0; } else { mv = v1; mi = i1; }
        for (int o = 16; o > 0; o >>= 1) {
            float ov = __shfl_xor_sync(0xffffffffu, mv, o);
            int   oi = __shfl_xor_sync(0xffffffffu, mi, o);
            if (ov > mv || (ov == mv && oi < mi)) { mv = ov; mi = oi; }
        }
        bv[k] = mv; bi[k] = mi;
        if (i0 == mi) v0 = NEG;
        if (i1 == mi) v1 = NEG;
    }
    float mx = bv[0];
    float s = 0.f, ev[TOPK];
    #pragma unroll
    for (int k = 0; k < TOPK; k++) { ev[k] = __expf(bv[k] - mx); s += ev[k]; }
    if (lane < TOPK) {
        g_topi[t*TOPK + lane] = bi[lane];
        g_topw[t*TOPK + lane] = ev[lane] / s;
        atomicAdd(&g_cnt[bi[lane]], 1);
    }
}

// Ordered compaction per expert: stable (slot-order) token lists
__global__ void build_lists() {
    int e = blockIdx.x;
    int tid = threadIdx.x;
    int lane = tid & 31, wid = tid >> 5;
    __shared__ int wcnt[8], wpre[8], stot;
    int base = g_off[e];
    int run = 0;
    for (int s0 = 0; s0 < TOT; s0 += 256) {
        int s = s0 + tid;
        bool p = (s < TOT) && (g_topi[s] == e);
        unsigned b = __ballot_sync(0xffffffffu, p);
        int wp = __popc(b & ((1u << lane) - 1u));
        if (lane == 0) wcnt[wid] = __popc(b);
        __syncthreads();
        if (tid == 0) {
            int a = 0;
            for (int w = 0; w < 8; w++) { wpre[w] = a; a += wcnt[w]; }
            stot = a;
        }
        __syncthreads();
        if (p) {
            int pos = base + run + wpre[wid] + wp;
            g_list[pos] = s / TOPK;
            g_lw[pos]   = g_topw[s];
        }
        run += stot;
        __syncthreads();
    }
}

// ---------------- repack kernels (coalesced both sides via smem) ----------------
// [H][E][N] -> [n][h][e]
__global__ void repack_gu(const float* __restrict__ src, float* __restrict__ dst) {
    __shared__ float s[32][33];
    int h = blockIdx.z;
    int e0 = blockIdx.x * 32, n0 = blockIdx.y * 32;
    int tx = threadIdx.x, ty = threadIdx.y;
    s[ty][tx] = src[(size_t)h*Ee*NEXP + (size_t)(e0+ty)*NEXP + (n0+tx)];
    __syncthreads();
    dst[(size_t)(n0+ty)*Hh*Ee + (size_t)h*Ee + (e0+tx)] = s[tx][ty];
}
// [E][H][N] -> [n][e][h]
__global__ void repack_dn(const float* __restrict__ src, float* __restrict__ dst) {
    __shared__ float s[32][33];
    int e = blockIdx.z;
    int h0 = blockIdx.x * 32, n0 = blockIdx.y * 32;
    int tx = threadIdx.x, ty = threadIdx.y;
    s[ty][tx] = src[(size_t)e*Hh*NEXP + (size_t)(h0+ty)*NEXP + (n0+tx)];
    __syncthreads();
    dst[(size_t)(n0+ty)*Ee*Hh + (size_t)e*Hh + (h0+tx)] = s[tx][ty];
}

// ---------------- unified 64x64x16 fp32 GEMM ----------------
// BLAY: 0 = B is [K][Ncols] (k-major, n contiguous; repacked expert weights)
//       1 = B is [Ncols][K] (n-major, k contiguous; nn.Linear weights)
// MODE: 0 = plain store C
//       1 = dual-B: C = silu(accB0) * accB1
//       2 = scatter: atomicAdd(out[token][col], acc * routing_weight)
// AMODE: 0 = A rows are plain (0..M)     (C rows = same)
//        1 = A rows gathered via g_list  (C rows = slot index base+gm)
//        2 = A rows are slots base+gm    (used by routed down; C via scatter)
template<int BLAY, int MODE, int AMODE>
__global__ __launch_bounds__(256) void gemm_k(
    const float* __restrict__ A, int lda,
    const float* __restrict__ Bg, const float* __restrict__ Bu, int ldb, size_t bStride,
    float* __restrict__ C, int ldc,
    int M, int K, int ntiles)
{
    const int mt = blockIdx.x;
    int e, nt;
    if (AMODE != 0) { e = blockIdx.y / ntiles; nt = blockIdx.y % ntiles; }
    else            { e = 0;                   nt = blockIdx.y; }
    const int m0 = mt * 64, n0 = nt * 64;
    int rows, base = 0;
    if (AMODE != 0) { rows = g_cnt[e]; base = g_off[e]; if (m0 >= rows) return; }
    else rows = M;
    const float* B0 = Bg + (size_t)e * bStride;
    const float* B1 = (MODE == 1) ? (Bu + (size_t)e * bStride) : nullptr;

    __shared__ __align__(16) float As [16][68];
    __shared__ __align__(16) float Bs0[16][68];
    __shared__ __align__(16) float Bs1[16][68];

    const int tid = threadIdx.x;
    const int tx = tid & 15, ty = tid >> 4;

    // A-load mapping: thread loads column (tid&15), rows (tid>>4)+16*i
    const int aCol  = tid & 15;
    const int aRow0 = tid >> 4;
    const float* aPtr[4];
    bool aOk[4];
    #pragma unroll
    for (int i = 0; i < 4; i++) {
        int gm = m0 + aRow0 + 16*i;
        bool ok = gm < rows;
        int r = 0;
        if (ok) {
            if (AMODE == 1)      r = g_list[base + gm];
            else if (AMODE == 2) r = base + gm;
            else                 r = gm;
        }
        aPtr[i] = A + (size_t)r * lda + aCol;
        aOk[i]  = ok;
    }

    float acc0[4][4], acc1[4][4];
    #pragma unroll
    for (int i = 0; i < 4; i++)
        #pragma unroll
        for (int j = 0; j < 4; j++) { acc0[i][j] = 0.f; acc1[i][j] = 0.f; }

    for (int k0 = 0; k0 < K; k0 += 16) {
        #pragma unroll
        for (int i = 0; i < 4; i++)
            As[aCol][aRow0 + 16*i] = aOk[i] ? aPtr[i][k0] : 0.f;

        if (BLAY == 0) {
            const int bN = tid & 63, bK0 = tid >> 6;
            #pragma unroll
            for (int i = 0; i < 4; i++) {
                int kk = bK0 + 4*i;
                size_t o = (size_t)(k0 + kk) * ldb + (n0 + bN);
                Bs0[kk][bN] = B0[o];
                if (MODE == 1) Bs1[kk][bN] = B1[o];
            }
        } else {
            const int bK = tid & 15, bN0 = tid >> 4;
            #pragma unroll
            for (int i = 0; i < 4; i++) {
                int n = bN0 + 16*i;
                size_t o = (size_t)(n0 + n) * ldb + (k0 + bK);
                Bs0[bK][n] = B0[o];
                if (MODE == 1) Bs1[bK][n] = B1[o];
            }
        }
        __syncthreads();

        #pragma unroll
        for (int kk = 0; kk < 16; kk++) {
            float4 a4 = *(const float4*)&As [kk][ty*4];
            float4 b4 = *(const float4*)&Bs0[kk][tx*4];
            float av[4] = {a4.x, a4.y, a4.z, a4.w};
            float bv[4] = {b4.x, b4.y, b4.z, b4.w};
            #pragma unroll
            for (int i = 0; i < 4; i++)
                #pragma unroll
                for (int j = 0; j < 4; j++)
                    acc0[i][j] += av[i] * bv[j];
            if (MODE == 1) {
                float4 c4 = *(const float4*)&Bs1[kk][tx*4];
                float cv[4] = {c4.x, c4.y, c4.z, c4.w};
                #pragma unroll
                for (int i = 0; i < 4; i++)
                    #pragma unroll
                    for (int j = 0; j < 4; j++)
                        acc1[i][j] += av[i] * cv[j];
            }
        }
        __syncthreads();
    }

    #pragma unroll
    for (int i = 0; i < 4; i++) {
        int gm = m0 + ty*4 + i;
        if (AMODE != 0 && gm >= rows) continue;
        #pragma unroll
        for (int j = 0; j < 4; j++) {
            int col = n0 + tx*4 + j;
            if (MODE == 0) {
                C[(size_t)gm * ldc + col] = acc0[i][j];
            } else if (MODE == 1) {
                float g = acc0[i][j], u = acc1[i][j];
                int rc = (AMODE != 0) ? (base + gm) : gm;
                C[(size_t)rc * ldc + col] = g / (1.f + __expf(-g)) * u;
            } else { // MODE == 2
                float w  = g_lw[base + gm];
                int  tok = g_list[base + gm];
                atomicAdd(&C[(size_t)tok * ldc + col], acc0[i][j] * w);
            }
        }
    }
}

// ---------------- launch ----------------
extern "C" void kernel_launch(void* const* d_in, const int* in_sizes, int n_in,
                              void* d_out, int out_size) {
    const float* x      = (const float*)d_in[0];   // [2048,1280]
    const float* wr     = (const float*)d_in[1];   // [64,1280]
    const float* wgexp  = (const float*)d_in[2];   // [1280,896,64]
    const float* wuexp  = (const float*)d_in[3];   // [1280,896,64]
    const float* wdexp  = (const float*)d_in[4];   // [896,1280,64]
    const float* wsg    = (const float*)d_in[5];   // [1792,1280]
    const float* wsu    = (const float*)d_in[6];   // [1792,1280]
    const float* wsd    = (const float*)d_in[7];   // [1280,1792]
    float* out = (float*)d_out;                    // [2048,1280]

    float *pWg, *pWu, *pWd, *pLog, *pAct, *pSh;
    cudaGetSymbolAddress((void**)&pWg,  g_Wg);
    cudaGetSymbolAddress((void**)&pWu,  g_Wu);
    cudaGetSymbolAddress((void**)&pWd,  g_Wd);
    cudaGetSymbolAddress((void**)&pLog, g_logits);
    cudaGetSymbolAddress((void**)&pAct, g_act);
    cudaGetSymbolAddress((void**)&pSh,  g_sh);

    // 1) router
    zero_cnt<<<1, 64>>>();
    gemm_k<1,0,0><<<dim3(BT/64, 1), 256>>>(x, Hh, wr, nullptr, Hh, 0, pLog, NEXP, BT, Hh, 1);
    router_topk<<<BT, 32>>>();
    scan_off<<<1, 32>>>();
    build_lists<<<NEXP, 256>>>();

    // 2) repack expert weights into coalesced per-expert layout
    repack_gu<<<dim3(Ee/32, NEXP/32, Hh), dim3(32,32)>>>(wgexp, pWg);
    repack_gu<<<dim3(Ee/32, NEXP/32, Hh), dim3(32,32)>>>(wuexp, pWu);
    repack_dn<<<dim3(Hh/32, NEXP/32, Ee), dim3(32,32)>>>(wdexp, pWd);

    // 3) shared experts: s = silu(x Wsg^T) * (x Wsu^T); out = s Wsd^T  (plain store fills out)
    gemm_k<1,1,0><<<dim3(BT/64, FFN/64), 256>>>(x, Hh, wsg, wsu, Hh, 0, pSh, FFN, BT, Hh, 1);
    gemm_k<1,0,0><<<dim3(BT/64, Hh/64), 256>>>(pSh, FFN, wsd, nullptr, FFN, 0, out, Hh, BT, FFN, 1);

    // 4) routed experts: grouped GEMMs over gathered tokens
    //    act[slot][e] = silu(x Wg) * (x Wu)
    gemm_k<0,1,1><<<dim3(BT/64, NEXP * (Ee/64)), 256>>>(
        x, Hh, pWg, pWu, Ee, (size_t)Hh*Ee, pAct, Ee, 0, Hh, Ee/64);
    //    out[token][h] += w_slot * (act Wd)   (atomic scatter after shared fills out)
    gemm_k<0,2,2><<<dim3(BT/64, NEXP * (Hh/64)), 256>>>(
        pAct, Ee, pWd, nullptr, Hh, (size_t)Ee*Hh, out, Hh, 0, Ee, Hh/64);
}

// round 3
// speedup vs baseline: 1.2763x; 1.2763x over previous
#include <cuda_runtime.h>
#include <cuda_bf16.h>
#include <cstdint>
#include <cstddef>

// Problem constants
#define BT   2048
#define Hh   1280
#define Ee   896
#define NEXP 64
#define TOPK 6
#define FFN  1792
#define TOT  (BT*TOPK)   // 12288 assignments

typedef __nv_bfloat16 bf16;

// ---------------- device scratch (no cudaMalloc allowed) ----------------
// Expert weights repacked to per-expert [n-row][k] bf16 hi/lo
__device__ bf16 g_Wg_h[(size_t)NEXP*Ee*Hh];  // gate: [exp][e][h]
__device__ bf16 g_Wg_l[(size_t)NEXP*Ee*Hh];
__device__ bf16 g_Wu_h[(size_t)NEXP*Ee*Hh];  // up:   [exp][e][h]
__device__ bf16 g_Wu_l[(size_t)NEXP*Ee*Hh];
__device__ bf16 g_Wd_h[(size_t)NEXP*Hh*Ee];  // down: [exp][h][e]
__device__ bf16 g_Wd_l[(size_t)NEXP*Hh*Ee];
// Shared weights split (layout already n-major from nn.Linear)
__device__ bf16 g_Sg_h[(size_t)FFN*Hh], g_Sg_l[(size_t)FFN*Hh];
__device__ bf16 g_Su_h[(size_t)FFN*Hh], g_Su_l[(size_t)FFN*Hh];
__device__ bf16 g_Sd_h[(size_t)Hh*FFN], g_Sd_l[(size_t)Hh*FFN];

__device__ float g_logits[BT*NEXP];
__device__ int   g_topi[TOT];
__device__ float g_topw[TOT];
__device__ int   g_cnt[NEXP];
__device__ int   g_off[NEXP];
__device__ int   g_list[TOT];
__device__ float g_lw[TOT];
__device__ float g_act[(size_t)TOT*Ee];      // silu(gate)*up per slot (fp32)
__device__ float g_sh[(size_t)BT*FFN];       // shared silu(g)*u (fp32)

// ---------------- small kernels ----------------
__global__ void zero_cnt() { if (threadIdx.x < NEXP) g_cnt[threadIdx.x] = 0; }

__global__ void scan_off() {
    if (threadIdx.x == 0) {
        int a = 0;
        for (int n = 0; n < NEXP; n++) { g_off[n] = a; a += g_cnt[n]; }
    }
}

__global__ void router_topk() {
    int t = blockIdx.x;
    int lane = threadIdx.x;
    const float NEG = __int_as_float(0xff800000);
    float v0 = g_logits[t*NEXP + lane];
    float v1 = g_logits[t*NEXP + 32 + lane];
    int i0 = lane, i1 = lane + 32;
    float bv[TOPK]; int bi[TOPK];
    for (int k = 0; k < TOPK; k++) {
        float mv; int mi;
        if (v0 > v1 || (v0 == v1 && i0 < i1)) { mv = v0; mi = i0; } else { mv = v1; mi = i1; }
        for (int o = 16; o > 0; o >>= 1) {
            float ov = __shfl_xor_sync(0xffffffffu, mv, o);
            int   oi = __shfl_xor_sync(0xffffffffu, mi, o);
            if (ov > mv || (ov == mv && oi < mi)) { mv = ov; mi = oi; }
        }
        bv[k] = mv; bi[k] = mi;
        if (i0 == mi) v0 = NEG;
        if (i1 == mi) v1 = NEG;
    }
    float mx = bv[0];
    float s = 0.f, ev[TOPK];
    #pragma unroll
    for (int k = 0; k < TOPK; k++) { ev[k] = __expf(bv[k] - mx); s += ev[k]; }
    if (lane < TOPK) {
        g_topi[t*TOPK + lane] = bi[lane];
        g_topw[t*TOPK + lane] = ev[lane] / s;
        atomicAdd(&g_cnt[bi[lane]], 1);
    }
}

__global__ void build_lists() {
    int e = blockIdx.x;
    int tid = threadIdx.x;
    int lane = tid & 31, wid = tid >> 5;
    __shared__ int wcnt[8], wpre[8], stot;
    int base = g_off[e];
    int run = 0;
    for (int s0 = 0; s0 < TOT; s0 += 256) {
        int s = s0 + tid;
        bool p = (s < TOT) && (g_topi[s] == e);
        unsigned b = __ballot_sync(0xffffffffu, p);
        int wp = __popc(b & ((1u << lane) - 1u));
        if (lane == 0) wcnt[wid] = __popc(b);
        __syncthreads();
        if (tid == 0) {
            int a = 0;
            for (int w = 0; w < 8; w++) { wpre[w] = a; a += wcnt[w]; }
            stot = a;
        }
        __syncthreads();
        if (p) {
            int pos = base + run + wpre[wid] + wp;
            g_list[pos] = s / TOPK;
            g_lw[pos]   = g_topw[s];
        }
        run += stot;
        __syncthreads();
    }
}

// ---------------- repack + split kernels ----------------
__device__ __forceinline__ void split32(float v, bf16& h, bf16& l) {
    h = __float2bfloat16(v);
    l = __float2bfloat16(v - __bfloat162float(h));
}

// gate/up: src [H][E][N] -> dst [exp][e][h]  (tile transpose over (h,n) at fixed e)
__global__ void repack_gu_split(const float* __restrict__ src, bf16* __restrict__ dh, bf16* __restrict__ dl) {
    __shared__ float s[32][33];
    int e = blockIdx.z;
    int h0 = blockIdx.x * 32, n0 = blockIdx.y * 32;
    int tx = threadIdx.x, ty = threadIdx.y;
    s[ty][tx] = src[(size_t)(h0+ty)*Ee*NEXP + (size_t)e*NEXP + (n0+tx)];
    __syncthreads();
    float v = s[tx][ty];  // (h=h0+tx, n=n0+ty)
    bf16 hi, lo; split32(v, hi, lo);
    size_t o = (size_t)(n0+ty)*Ee*Hh + (size_t)e*Hh + (h0+tx);
    dh[o] = hi; dl[o] = lo;
}

// down: src [E][H][N] -> dst [exp][h][e]  (tile transpose over (e,n) at fixed h)
__global__ void repack_dn_split(const float* __restrict__ src, bf16* __restrict__ dh, bf16* __restrict__ dl) {
    __shared__ float s[32][33];
    int h = blockIdx.z;
    int e0 = blockIdx.x * 32, n0 = blockIdx.y * 32;
    int tx = threadIdx.x, ty = threadIdx.y;
    s[ty][tx] = src[(size_t)(e0+ty)*Hh*NEXP + (size_t)h*NEXP + (n0+tx)];
    __syncthreads();
    float v = s[tx][ty];  // (e=e0+tx, n=n0+ty)
    bf16 hi, lo; split32(v, hi, lo);
    size_t o = (size_t)(n0+ty)*Hh*Ee + (size_t)h*Ee + (e0+tx);
    dh[o] = hi; dl[o] = lo;
}

// elementwise split (shared weights; layout preserved)
__global__ void split_copy(const float* __restrict__ src, bf16* __restrict__ dh, bf16* __restrict__ dl, int n4) {
    int i = blockIdx.x * blockDim.x + threadIdx.x;
    if (i < n4) {
        float4 v = ((const float4*)src)[i];
        bf16 h0,l0,h1,l1,h2,l2,h3,l3;
        split32(v.x,h0,l0); split32(v.y,h1,l1); split32(v.z,h2,l2); split32(v.w,h3,l3);
        dh[i*4+0]=h0; dh[i*4+1]=h1; dh[i*4+2]=h2; dh[i*4+3]=h3;
        dl[i*4+0]=l0; dl[i*4+1]=l1; dl[i*4+2]=l2; dl[i*4+3]=l3;
    }
}

// ---------------- fp32 router GEMM (kept from R1; top-k ordering must match ref) ----------------
__global__ __launch_bounds__(256) void router_gemm(
    const float* __restrict__ A, const float* __restrict__ B, float* __restrict__ C)
{
    // A [BT][Hh], B [64][Hh] n-major, C [BT][64]; tile 64x64x16
    const int m0 = blockIdx.x * 64;
    __shared__ __align__(16) float As[16][68];
    __shared__ __align__(16) float Bs[16][68];
    const int tid = threadIdx.x;
    const int tx = tid & 15, ty = tid >> 4;
    float acc[4][4];
    #pragma unroll
    for (int i = 0; i < 4; i++) for (int j = 0; j < 4; j++) acc[i][j] = 0.f;
    const int aCol = tid & 15, aRow0 = tid >> 4;
    for (int k0 = 0; k0 < Hh; k0 += 16) {
        #pragma unroll
        for (int i = 0; i < 4; i++)
            As[aCol][aRow0 + 16*i] = A[(size_t)(m0 + aRow0 + 16*i)*Hh + k0 + aCol];
        const int bK = tid & 15, bN0 = tid >> 4;
        #pragma unroll
        for (int i = 0; i < 4; i++)
            Bs[bK][bN0 + 16*i] = B[(size_t)(bN0 + 16*i)*Hh + k0 + bK];
        __syncthreads();
        #pragma unroll
        for (int kk = 0; kk < 16; kk++) {
            float4 a4 = *(const float4*)&As[kk][ty*4];
            float4 b4 = *(const float4*)&Bs[kk][tx*4];
            float av[4] = {a4.x,a4.y,a4.z,a4.w};
            float bv[4] = {b4.x,b4.y,b4.z,b4.w};
            #pragma unroll
            for (int i = 0; i < 4; i++) for (int j = 0; j < 4; j++) acc[i][j] += av[i]*bv[j];
        }
        __syncthreads();
    }
    #pragma unroll
    for (int i = 0; i < 4; i++) for (int j = 0; j < 4; j++)
        C[(size_t)(m0 + ty*4 + i)*NEXP + tx*4 + j] = acc[i][j];
}

// ---------------- MMA helpers ----------------
__device__ __forceinline__ void ldsm_x4(uint32_t* r, const void* p) {
    uint32_t a = (uint32_t)__cvta_generic_to_shared(p);
    asm volatile("ldmatrix.sync.aligned.m8n8.x4.shared.b16 {%0,%1,%2,%3}, [%4];"
        : "=r"(r[0]), "=r"(r[1]), "=r"(r[2]), "=r"(r[3]) : "r"(a));
}
__device__ __forceinline__ void ldsm_x2(uint32_t* r, const void* p) {
    uint32_t a = (uint32_t)__cvta_generic_to_shared(p);
    asm volatile("ldmatrix.sync.aligned.m8n8.x2.shared.b16 {%0,%1}, [%2];"
        : "=r"(r[0]), "=r"(r[1]) : "r"(a));
}
__device__ __forceinline__ void mma16816(float* d, const uint32_t* a, const uint32_t* b) {
    asm volatile("mma.sync.aligned.m16n8k16.row.col.f32.bf16.bf16.f32 "
        "{%0,%1,%2,%3}, {%4,%5,%6,%7}, {%8,%9}, {%0,%1,%2,%3};"
        : "+f"(d[0]), "+f"(d[1]), "+f"(d[2]), "+f"(d[3])
        : "r"(a[0]), "r"(a[1]), "r"(a[2]), "r"(a[3]), "r"(b[0]), "r"(b[1]));
}

// ---------------- split-bf16 tensor-core GEMM: 128x64x32 tile, 8 warps ----------------
// A fp32 (split on load). B bf16 hi/lo, per-expert layout [n][K] (k contiguous).
// MODE: 0 = plain store, 1 = dual-B silu(g)*u store, 2 = atomic scatter with routing weight
// AMODE: 0 = plain rows, 1 = gather via g_list (C rows = slot), 2 = rows are slots
template<int MODE, int AMODE>
__global__ __launch_bounds__(256) void mma_gemm(
    const float* __restrict__ A, int lda,
    const bf16* __restrict__ B0h, const bf16* __restrict__ B0l,
    const bf16* __restrict__ B1h, const bf16* __restrict__ B1l,
    size_t bStride, float* __restrict__ C, int ldc,
    int M, int K, int ntiles)
{
    constexpr int NB = (MODE == 1) ? 4 : 2;
    __shared__ __align__(16) bf16 sAh[128][40];
    __shared__ __align__(16) bf16 sAl[128][40];
    __shared__ __align__(16) bf16 sB[NB][64][40];

    const int mt = blockIdx.x;
    int e, nt;
    if (AMODE != 0) { e = blockIdx.y / ntiles; nt = blockIdx.y % ntiles; }
    else            { e = 0;                   nt = blockIdx.y; }
    const int m0 = mt * 128, n0 = nt * 64;
    int rows, base = 0;
    if (AMODE != 0) { rows = g_cnt[e]; base = g_off[e]; if (m0 >= rows) return; }
    else rows = M;

    const bf16* bsrc[NB];
    bsrc[0] = B0h + (size_t)e * bStride;
    bsrc[1] = B0l + (size_t)e * bStride;
    if (MODE == 1) { bsrc[2] = B1h + (size_t)e * bStride; bsrc[3] = B1l + (size_t)e * bStride; }

    const int tid = threadIdx.x, lane = tid & 31, wid = tid >> 5;
    const int wr = wid >> 1, wc = wid & 1;   // warp grid 4x2 (m x n), warp tile 32x32

    // A gmem load mapping: 32 rows x 32 k per pass (4 passes), float4 per thread
    const int ar = tid >> 3, akq = (tid & 7) * 4;
    const float* aPtr[4];
    bool aOk[4];
    #pragma unroll
    for (int p = 0; p < 4; p++) {
        int gm = m0 + ar + 32*p;
        bool ok = gm < rows;
        int r = 0;
        if (ok) {
            if (AMODE == 1)      r = g_list[base + gm];
            else if (AMODE == 2) r = base + gm;
            else                 r = gm;
        }
        aPtr[p] = A + (size_t)r * lda + akq;
        aOk[p]  = ok;
    }
    // B gmem load mapping: 64 rows, 4 threads/row, uint4 (8 bf16) per thread
    const int bn = tid >> 2, bkq = (tid & 3) * 8;

    float accg[2][4][4];
    float accu[MODE == 1 ? 2 : 1][4][4];
    #pragma unroll
    for (int fm = 0; fm < 2; fm++)
        #pragma unroll
        for (int fn = 0; fn < 4; fn++)
            #pragma unroll
            for (int q = 0; q < 4; q++) {
                accg[fm][fn][q] = 0.f;
                if (MODE == 1) accu[fm][fn][q] = 0.f;
            }

    for (int k0 = 0; k0 < K; k0 += 32) {
        #pragma unroll
        for (int p = 0; p < 4; p++) {
            float4 v = aOk[p] ? *(const float4*)(aPtr[p] + k0) : make_float4(0.f,0.f,0.f,0.f);
            int row = ar + 32*p;
            bf16 h, l;
            split32(v.x, h, l); sAh[row][akq+0] = h; sAl[row][akq+0] = l;
            split32(v.y, h, l); sAh[row][akq+1] = h; sAl[row][akq+1] = l;
            split32(v.z, h, l); sAh[row][akq+2] = h; sAl[row][akq+2] = l;
            split32(v.w, h, l); sAh[row][akq+3] = h; sAl[row][akq+3] = l;
        }
        #pragma unroll
        for (int arr = 0; arr < NB; arr++) {
            uint4 v = *(const uint4*)&bsrc[arr][(size_t)(n0 + bn) * K + k0 + bkq];
            *(uint4*)&sB[arr][bn][bkq] = v;
        }
        __syncthreads();

        #pragma unroll
        for (int kk = 0; kk < 32; kk += 16) {
            uint32_t ah[2][4], al[2][4];
            #pragma unroll
            for (int fm = 0; fm < 2; fm++) {
                int arow = wr*32 + fm*16 + (lane & 15);
                int acol = kk + (lane >> 4) * 8;
                ldsm_x4(ah[fm], &sAh[arow][acol]);
                ldsm_x4(al[fm], &sAl[arow][acol]);
            }
            #pragma unroll
            for (int fn = 0; fn < 4; fn++) {
                int nrow = wc*32 + fn*8 + (lane & 7);
                int kcol = kk + ((lane >> 3) & 1) * 8;
                uint32_t b0h[2], b0l[2];
                ldsm_x2(b0h, &sB[0][nrow][kcol]);
                ldsm_x2(b0l, &sB[1][nrow][kcol]);
                #pragma unroll
                for (int fm = 0; fm < 2; fm++) {
                    mma16816(accg[fm][fn], ah[fm], b0h);
                    mma16816(accg[fm][fn], ah[fm], b0l);
                    mma16816(accg[fm][fn], al[fm], b0h);
                }
                if (MODE == 1) {
                    uint32_t b1h[2], b1l[2];
                    ldsm_x2(b1h, &sB[2][nrow][kcol]);
                    ldsm_x2(b1l, &sB[3][nrow][kcol]);
                    #pragma unroll
                    for (int fm = 0; fm < 2; fm++) {
                        mma16816(accu[fm][fn], ah[fm], b1h);
                        mma16816(accu[fm][fn], ah[fm], b1l);
                        mma16816(accu[fm][fn], al[fm], b1h);
                    }
                }
            }
        }
        __syncthreads();
    }

    // epilogue
    #pragma unroll
    for (int fm = 0; fm < 2; fm++) {
        int rbase = m0 + wr*32 + fm*16 + (lane >> 2);
        #pragma unroll
        for (int half = 0; half < 2; half++) {
            int gm = rbase + half*8;
            if (AMODE != 0 && gm >= rows) continue;
            #pragma unroll
            for (int fn = 0; fn < 4; fn++) {
                int col = n0 + wc*32 + fn*8 + (lane & 3)*2;
                float c0 = accg[fm][fn][half*2+0];
                float c1 = accg[fm][fn][half*2+1];
                if (MODE == 0) {
                    *(float2*)&C[(size_t)gm * ldc + col] = make_float2(c0, c1);
                } else if (MODE == 1) {
                    float u0 = accu[fm][fn][half*2+0];
                    float u1 = accu[fm][fn][half*2+1];
                    float s0 = c0 / (1.f + __expf(-c0)) * u0;
                    float s1 = c1 / (1.f + __expf(-c1)) * u1;
                    int rc = (AMODE != 0) ? (base + gm) : gm;
                    *(float2*)&C[(size_t)rc * ldc + col] = make_float2(s0, s1);
                } else {
                    float w  = g_lw[base + gm];
                    int  tok = g_list[base + gm];
                    atomicAdd(&C[(size_t)tok * ldc + col + 0], c0 * w);
                    atomicAdd(&C[(size_t)tok * ldc + col + 1], c1 * w);
                }
            }
        }
    }
}

// ---------------- launch ----------------
extern "C" void kernel_launch(void* const* d_in, const int* in_sizes, int n_in,
                              void* d_out, int out_size) {
    const float* x      = (const float*)d_in[0];   // [2048,1280]
    const float* wr     = (const float*)d_in[1];   // [64,1280]
    const float* wgexp  = (const float*)d_in[2];   // [1280,896,64]
    const float* wuexp  = (const float*)d_in[3];   // [1280,896,64]
    const float* wdexp  = (const float*)d_in[4];   // [896,1280,64]
    const float* wsg    = (const float*)d_in[5];   // [1792,1280]
    const float* wsu    = (const float*)d_in[6];   // [1792,1280]
    const float* wsd    = (const float*)d_in[7];   // [1280,1792]
    float* out = (float*)d_out;                    // [2048,1280]

    float *pLog, *pAct, *pSh;
    bf16 *pWg_h,*pWg_l,*pWu_h,*pWu_l,*pWd_h,*pWd_l;
    bf16 *pSg_h,*pSg_l,*pSu_h,*pSu_l,*pSd_h,*pSd_l;
    cudaGetSymbolAddress((void**)&pLog, g_logits);
    cudaGetSymbolAddress((void**)&pAct, g_act);
    cudaGetSymbolAddress((void**)&pSh,  g_sh);
    cudaGetSymbolAddress((void**)&pWg_h, g_Wg_h); cudaGetSymbolAddress((void**)&pWg_l, g_Wg_l);
    cudaGetSymbolAddress((void**)&pWu_h, g_Wu_h); cudaGetSymbolAddress((void**)&pWu_l, g_Wu_l);
    cudaGetSymbolAddress((void**)&pWd_h, g_Wd_h); cudaGetSymbolAddress((void**)&pWd_l, g_Wd_l);
    cudaGetSymbolAddress((void**)&pSg_h, g_Sg_h); cudaGetSymbolAddress((void**)&pSg_l, g_Sg_l);
    cudaGetSymbolAddress((void**)&pSu_h, g_Su_h); cudaGetSymbolAddress((void**)&pSu_l, g_Su_l);
    cudaGetSymbolAddress((void**)&pSd_h, g_Sd_h); cudaGetSymbolAddress((void**)&pSd_l, g_Sd_l);

    // 1) router (fp32 — ordering near ties must match reference)
    zero_cnt<<<1, 64>>>();
    router_gemm<<<BT/64, 256>>>(x, wr, pLog);
    router_topk<<<BT, 32>>>();
    scan_off<<<1, 32>>>();
    build_lists<<<NEXP, 256>>>();

    // 2) repack + split weights
    repack_gu_split<<<dim3(Hh/32, NEXP/32, Ee), dim3(32,32)>>>(wgexp, pWg_h, pWg_l);
    repack_gu_split<<<dim3(Hh/32, NEXP/32, Ee), dim3(32,32)>>>(wuexp, pWu_h, pWu_l);
    repack_dn_split<<<dim3(Ee/32, NEXP/32, Hh), dim3(32,32)>>>(wdexp, pWd_h, pWd_l);
    split_copy<<<(FFN*Hh/4 + 255)/256, 256>>>(wsg, pSg_h, pSg_l, FFN*Hh/4);
    split_copy<<<(FFN*Hh/4 + 255)/256, 256>>>(wsu, pSu_h, pSu_l, FFN*Hh/4);
    split_copy<<<(Hh*FFN/4 + 255)/256, 256>>>(wsd, pSd_h, pSd_l, Hh*FFN/4);

    // 3) shared experts
    mma_gemm<1,0><<<dim3(BT/128, FFN/64), 256>>>(
        x, Hh, pSg_h, pSg_l, pSu_h, pSu_l, 0, pSh, FFN, BT, Hh, 1);
    mma_gemm<0,0><<<dim3(BT/128, Hh/64), 256>>>(
        pSh, FFN, pSd_h, pSd_l, nullptr, nullptr, 0, out, Hh, BT, FFN, 1);

    // 4) routed experts (grouped, gathered)
    mma_gemm<1,1><<<dim3(BT/128, NEXP*(Ee/64)), 256>>>(
        x, Hh, pWg_h, pWg_l, pWu_h, pWu_l, (size_t)Ee*Hh, pAct, Ee, 0, Hh, Ee/64);
    mma_gemm<2,2><<<dim3(BT/128, NEXP*(Hh/64)), 256>>>(
        pAct, Ee, pWd_h, pWd_l, nullptr, nullptr, (size_t)Hh*Ee, out, Hh, 0, Ee, Hh/64);
}

// round 4
// speedup vs baseline: 1.8604x; 1.4576x over previous
#include <cuda_runtime.h>
#include <cuda_bf16.h>
#include <cstdint>
#include <cstddef>

#define BT   2048
#define Hh   1280
#define Ee   896
#define NEXP 64
#define TOPK 6
#define FFN  1792
#define TOT  (BT*TOPK)

typedef __nv_bfloat16 bf16;

// ---------------- device scratch ----------------
__device__ bf16 g_Wg_h[(size_t)NEXP*Ee*Hh];
__device__ bf16 g_Wg_l[(size_t)NEXP*Ee*Hh];
__device__ bf16 g_Wu_h[(size_t)NEXP*Ee*Hh];
__device__ bf16 g_Wu_l[(size_t)NEXP*Ee*Hh];
__device__ bf16 g_Wd_h[(size_t)NEXP*Hh*Ee];
__device__ bf16 g_Wd_l[(size_t)NEXP*Hh*Ee];
__device__ bf16 g_Sg_h[(size_t)FFN*Hh], g_Sg_l[(size_t)FFN*Hh];
__device__ bf16 g_Su_h[(size_t)FFN*Hh], g_Su_l[(size_t)FFN*Hh];
__device__ bf16 g_Sd_h[(size_t)Hh*FFN], g_Sd_l[(size_t)Hh*FFN];

__device__ bf16 g_xh[(size_t)BT*Hh],  g_xl[(size_t)BT*Hh];     // split input
__device__ bf16 g_shh[(size_t)BT*FFN], g_shl[(size_t)BT*FFN];  // shared act hi/lo
__device__ bf16 g_acth[(size_t)TOT*Ee], g_actl[(size_t)TOT*Ee];// routed act hi/lo
__device__ float g_dout[(size_t)TOT*Hh];                        // per-slot down out (weighted)

__device__ float g_logits[BT*NEXP];
__device__ int   g_topi[TOT];
__device__ float g_topw[TOT];
__device__ int   g_cnt[NEXP];
__device__ int   g_off[NEXP];
__device__ int   g_list[TOT];
__device__ float g_lw[TOT];
__device__ int   g_pos[TOT];   // slot position for (token, k)

// ---------------- small kernels ----------------
__global__ void zero_cnt() { if (threadIdx.x < NEXP) g_cnt[threadIdx.x] = 0; }

__global__ void scan_off() {
    if (threadIdx.x == 0) {
        int a = 0;
        for (int n = 0; n < NEXP; n++) { g_off[n] = a; a += g_cnt[n]; }
    }
}

__global__ void router_topk() {
    int t = blockIdx.x;
    int lane = threadIdx.x;
    const float NEG = __int_as_float(0xff800000);
    float v0 = g_logits[t*NEXP + lane];
    float v1 = g_logits[t*NEXP + 32 + lane];
    int i0 = lane, i1 = lane + 32;
    float bv[TOPK]; int bi[TOPK];
    for (int k = 0; k < TOPK; k++) {
        float mv; int mi;
        if (v0 > v1 || (v0 == v1 && i0 < i1)) { mv = v0; mi = i0; } else { mv = v1; mi = i1; }
        for (int o = 16; o > 0; o >>= 1) {
            float ov = __shfl_xor_sync(0xffffffffu, mv, o);
            int   oi = __shfl_xor_sync(0xffffffffu, mi, o);
            if (ov > mv || (ov == mv && oi < mi)) { mv = ov; mi = oi; }
        }
        bv[k] = mv; bi[k] = mi;
        if (i0 == mi) v0 = NEG;
        if (i1 == mi) v1 = NEG;
    }
    float mx = bv[0];
    float s = 0.f, ev[TOPK];
    #pragma unroll
    for (int k = 0; k < TOPK; k++) { ev[k] = __expf(bv[k] - mx); s += ev[k]; }
    if (lane < TOPK) {
        g_topi[t*TOPK + lane] = bi[lane];
        g_topw[t*TOPK + lane] = ev[lane] / s;
        atomicAdd(&g_cnt[bi[lane]], 1);
    }
}

__global__ void build_lists() {
    int e = blockIdx.x;
    int tid = threadIdx.x;
    int lane = tid & 31, wid = tid >> 5;
    __shared__ int wcnt[8], wpre[8], stot;
    int base = g_off[e];
    int run = 0;
    for (int s0 = 0; s0 < TOT; s0 += 256) {
        int s = s0 + tid;
        bool p = (s < TOT) && (g_topi[s] == e);
        unsigned b = __ballot_sync(0xffffffffu, p);
        int wp = __popc(b & ((1u << lane) - 1u));
        if (lane == 0) wcnt[wid] = __popc(b);
        __syncthreads();
        if (tid == 0) {
            int a = 0;
            for (int w = 0; w < 8; w++) { wpre[w] = a; a += wcnt[w]; }
            stot = a;
        }
        __syncthreads();
        if (p) {
            int pos = base + run + wpre[wid] + wp;
            g_list[pos] = s / TOPK;
            g_lw[pos]   = g_topw[s];
            g_pos[s]    = pos;
        }
        run += stot;
        __syncthreads();
    }
}

// ---------------- split / repack ----------------
__device__ __forceinline__ void split32(float v, bf16& h, bf16& l) {
    h = __float2bfloat16(v);
    l = __float2bfloat16(v - __bfloat162float(h));
}

__global__ void repack_gu_split(const float* __restrict__ src, bf16* __restrict__ dh, bf16* __restrict__ dl) {
    __shared__ float s[32][33];
    int e = blockIdx.z;
    int h0 = blockIdx.x * 32, n0 = blockIdx.y * 32;
    int tx = threadIdx.x, ty = threadIdx.y;
    s[ty][tx] = src[(size_t)(h0+ty)*Ee*NEXP + (size_t)e*NEXP + (n0+tx)];
    __syncthreads();
    float v = s[tx][ty];
    bf16 hi, lo; split32(v, hi, lo);
    size_t o = (size_t)(n0+ty)*Ee*Hh + (size_t)e*Hh + (h0+tx);
    dh[o] = hi; dl[o] = lo;
}

__global__ void repack_dn_split(const float* __restrict__ src, bf16* __restrict__ dh, bf16* __restrict__ dl) {
    __shared__ float s[32][33];
    int h = blockIdx.z;
    int e0 = blockIdx.x * 32, n0 = blockIdx.y * 32;
    int tx = threadIdx.x, ty = threadIdx.y;
    s[ty][tx] = src[(size_t)(e0+ty)*Hh*NEXP + (size_t)h*NEXP + (n0+tx)];
    __syncthreads();
    float v = s[tx][ty];
    bf16 hi, lo; split32(v, hi, lo);
    size_t o = (size_t)(n0+ty)*Hh*Ee + (size_t)h*Ee + (e0+tx);
    dh[o] = hi; dl[o] = lo;
}

__global__ void split_copy(const float* __restrict__ src, bf16* __restrict__ dh, bf16* __restrict__ dl, int n4) {
    int i = blockIdx.x * blockDim.x + threadIdx.x;
    if (i < n4) {
        float4 v = ((const float4*)src)[i];
        bf16 h0,l0,h1,l1,h2,l2,h3,l3;
        split32(v.x,h0,l0); split32(v.y,h1,l1); split32(v.z,h2,l2); split32(v.w,h3,l3);
        dh[i*4+0]=h0; dh[i*4+1]=h1; dh[i*4+2]=h2; dh[i*4+3]=h3;
        dl[i*4+0]=l0; dl[i*4+1]=l1; dl[i*4+2]=l2; dl[i*4+3]=l3;
    }
}

// ---------------- fp32 router GEMM ----------------
__global__ __launch_bounds__(256) void router_gemm(
    const float* __restrict__ A, const float* __restrict__ B, float* __restrict__ C)
{
    const int m0 = blockIdx.x * 64;
    __shared__ __align__(16) float As[16][68];
    __shared__ __align__(16) float Bs[16][68];
    const int tid = threadIdx.x;
    const int tx = tid & 15, ty = tid >> 4;
    float acc[4][4];
    #pragma unroll
    for (int i = 0; i < 4; i++) for (int j = 0; j < 4; j++) acc[i][j] = 0.f;
    const int aCol = tid & 15, aRow0 = tid >> 4;
    for (int k0 = 0; k0 < Hh; k0 += 16) {
        #pragma unroll
        for (int i = 0; i < 4; i++)
            As[aCol][aRow0 + 16*i] = A[(size_t)(m0 + aRow0 + 16*i)*Hh + k0 + aCol];
        const int bK = tid & 15, bN0 = tid >> 4;
        #pragma unroll
        for (int i = 0; i < 4; i++)
            Bs[bK][bN0 + 16*i] = B[(size_t)(bN0 + 16*i)*Hh + k0 + bK];
        __syncthreads();
        #pragma unroll
        for (int kk = 0; kk < 16; kk++) {
            float4 a4 = *(const float4*)&As[kk][ty*4];
            float4 b4 = *(const float4*)&Bs[kk][tx*4];
            float av[4] = {a4.x,a4.y,a4.z,a4.w};
            float bv[4] = {b4.x,b4.y,b4.z,b4.w};
            #pragma unroll
            for (int i = 0; i < 4; i++) for (int j = 0; j < 4; j++) acc[i][j] += av[i]*bv[j];
        }
        __syncthreads();
    }
    #pragma unroll
    for (int i = 0; i < 4; i++) for (int j = 0; j < 4; j++)
        C[(size_t)(m0 + ty*4 + i)*NEXP + tx*4 + j] = acc[i][j];
}

// ---------------- MMA / cp.async helpers ----------------
__device__ __forceinline__ void ldsm_x4(uint32_t* r, const void* p) {
    uint32_t a = (uint32_t)__cvta_generic_to_shared(p);
    asm volatile("ldmatrix.sync.aligned.m8n8.x4.shared.b16 {%0,%1,%2,%3}, [%4];"
        : "=r"(r[0]), "=r"(r[1]), "=r"(r[2]), "=r"(r[3]) : "r"(a));
}
__device__ __forceinline__ void ldsm_x2(uint32_t* r, const void* p) {
    uint32_t a = (uint32_t)__cvta_generic_to_shared(p);
    asm volatile("ldmatrix.sync.aligned.m8n8.x2.shared.b16 {%0,%1}, [%2];"
        : "=r"(r[0]), "=r"(r[1]) : "r"(a));
}
__device__ __forceinline__ void mma16816(float* d, const uint32_t* a, const uint32_t* b) {
    asm volatile("mma.sync.aligned.m16n8k16.row.col.f32.bf16.bf16.f32 "
        "{%0,%1,%2,%3}, {%4,%5,%6,%7}, {%8,%9}, {%0,%1,%2,%3};"
        : "+f"(d[0]), "+f"(d[1]), "+f"(d[2]), "+f"(d[3])
        : "r"(a[0]), "r"(a[1]), "r"(a[2]), "r"(a[3]), "r"(b[0]), "r"(b[1]));
}
__device__ __forceinline__ void cp16(uint32_t dst, const void* src, bool pred) {
    int sz = pred ? 16 : 0;
    asm volatile("cp.async.ca.shared.global [%0], [%1], 16, %2;"
        :: "r"(dst), "l"(src), "r"(sz));
}
__device__ __forceinline__ void cp_commit() { asm volatile("cp.async.commit_group;" ::: "memory"); }
template<int N> __device__ __forceinline__ void cp_wait() { asm volatile("cp.async.wait_group %0;" :: "n"(N) : "memory"); }

// ---------------- pipelined split-bf16 MMA GEMM ----------------
// 128x64x32 tile, 8 warps, 2-stage cp.async double buffer.
// A: bf16 hi/lo [rows][K] (k contiguous). B: bf16 hi/lo per-expert [n][K].
// MODE: 0 = fp32 store to C, 1 = dual-B silu(g)*u -> split store to Ch/Cl,
//       2 = fp32 store acc * g_lw[slot] to C (rows are slots)
// AMODE: 0 = plain rows, 1 = gather via g_list (C rows = slot), 2 = rows are slots
template<int MODE, int AMODE>
__global__ __launch_bounds__(256) void mma2(
    const bf16* __restrict__ Ah, const bf16* __restrict__ Al, int lda,
    const bf16* __restrict__ B0h, const bf16* __restrict__ B0l,
    const bf16* __restrict__ B1h, const bf16* __restrict__ B1l,
    size_t bStride,
    float* __restrict__ C, bf16* __restrict__ Ch, bf16* __restrict__ Cl,
    int ldc, int M, int K, int ntiles)
{
    constexpr int NB = (MODE == 1) ? 4 : 2;
    constexpr int OFF_AL = 128*40;
    constexpr int OFF_B  = 2*128*40;
    constexpr int STG    = 2*128*40 + NB*64*40;   // elems per stage
    extern __shared__ __align__(16) bf16 sm[];

    const int mt = blockIdx.x;
    int e, nt;
    if (AMODE != 0) { e = blockIdx.y / ntiles; nt = blockIdx.y % ntiles; }
    else            { e = 0;                   nt = blockIdx.y; }
    const int m0 = mt * 128, n0 = nt * 64;
    int rows, base = 0;
    if (AMODE != 0) { rows = g_cnt[e]; base = g_off[e]; if (m0 >= rows) return; }
    else rows = M;

    const bf16* bsrc[NB];
    bsrc[0] = B0h + (size_t)e * bStride;
    bsrc[1] = B0l + (size_t)e * bStride;
    if (MODE == 1) { bsrc[2] = B1h + (size_t)e * bStride; bsrc[3] = B1l + (size_t)e * bStride; }

    const int tid = threadIdx.x, lane = tid & 31, wid = tid >> 5;
    const int wr = wid >> 1, wc = wid & 1;

    const uint32_t smbase = (uint32_t)__cvta_generic_to_shared(sm);

    // A cp.async mapping: 4 chunks/thread covering {hi,lo} x 128 rows x 32 cols
    const bf16* aSrc[4];
    uint32_t aDst[4];
    bool aOk[4];
    #pragma unroll
    for (int i = 0; i < 4; i++) {
        int idx = i*256 + tid;
        int a = idx >> 9, rem = idx & 511;
        int r = rem >> 2, q = rem & 3;
        int gm = m0 + r;
        bool ok = gm < rows;
        int row = 0;
        if (ok) {
            if (AMODE == 1)      row = g_list[base + gm];
            else if (AMODE == 2) row = base + gm;
            else                 row = gm;
        }
        const bf16* src = (a ? Al : Ah) + (size_t)row * lda + q*8;
        aSrc[i] = src;
        aOk[i]  = ok;
        aDst[i] = (uint32_t)(((a ? OFF_AL : 0) + r*40 + q*8) * 2);
    }
    // B cp.async mapping: NB chunks/thread
    const bf16* bSrc[NB];
    uint32_t bDst[NB];
    #pragma unroll
    for (int i = 0; i < NB; i++) {
        int idx = i*256 + tid;
        int arr = idx >> 8, rem = idx & 255;
        int r = rem >> 2, q = rem & 3;
        bSrc[i] = bsrc[arr] + (size_t)(n0 + r) * K + q*8;
        bDst[i] = (uint32_t)((OFF_B + arr*64*40 + r*40 + q*8) * 2);
    }

    float accg[2][4][4];
    float accu[MODE == 1 ? 2 : 1][4][4];
    #pragma unroll
    for (int fm = 0; fm < 2; fm++)
        #pragma unroll
        for (int fn = 0; fn < 4; fn++)
            #pragma unroll
            for (int q = 0; q < 4; q++) {
                accg[fm][fn][q] = 0.f;
                if (MODE == 1) accu[fm][fn][q] = 0.f;
            }

    const int nk = K / 32;

    // prologue: prefetch tile 0 into stage 0
    {
        const uint32_t sb = smbase;
        #pragma unroll
        for (int i = 0; i < 4; i++) cp16(sb + aDst[i], aSrc[i], aOk[i]);
        #pragma unroll
        for (int i = 0; i < NB; i++) cp16(sb + bDst[i], bSrc[i], true);
        cp_commit();
    }

    for (int kt = 0; kt < nk; kt++) {
        const int st = kt & 1;
        if (kt + 1 < nk) {
            const int k0 = (kt + 1) * 32;
            const uint32_t sb = smbase + (uint32_t)((st ^ 1) * STG * 2);
            #pragma unroll
            for (int i = 0; i < 4; i++) cp16(sb + aDst[i], aSrc[i] + k0, aOk[i]);
            #pragma unroll
            for (int i = 0; i < NB; i++) cp16(sb + bDst[i], bSrc[i] + k0, true);
            cp_commit();
            cp_wait<1>();
        } else {
            cp_wait<0>();
        }
        __syncthreads();

        bf16* pAh = sm + st * STG;
        bf16* pAl = pAh + OFF_AL;
        bf16* pB  = pAh + OFF_B;

        #pragma unroll
        for (int kk = 0; kk < 32; kk += 16) {
            uint32_t ah[2][4], al[2][4];
            #pragma unroll
            for (int fm = 0; fm < 2; fm++) {
                int arow = wr*32 + fm*16 + (lane & 15);
                int acol = kk + (lane >> 4) * 8;
                ldsm_x4(ah[fm], pAh + arow*40 + acol);
                ldsm_x4(al[fm], pAl + arow*40 + acol);
            }
            #pragma unroll
            for (int fn = 0; fn < 4; fn++) {
                int nrow = wc*32 + fn*8 + (lane & 7);
                int kcol = kk + ((lane >> 3) & 1) * 8;
                uint32_t b0h[2], b0l[2];
                ldsm_x2(b0h, pB + 0*64*40 + nrow*40 + kcol);
                ldsm_x2(b0l, pB + 1*64*40 + nrow*40 + kcol);
                #pragma unroll
                for (int fm = 0; fm < 2; fm++) {
                    mma16816(accg[fm][fn], ah[fm], b0h);
                    mma16816(accg[fm][fn], ah[fm], b0l);
                    mma16816(accg[fm][fn], al[fm], b0h);
                }
                if (MODE == 1) {
                    uint32_t b1h[2], b1l[2];
                    ldsm_x2(b1h, pB + 2*64*40 + nrow*40 + kcol);
                    ldsm_x2(b1l, pB + 3*64*40 + nrow*40 + kcol);
                    #pragma unroll
                    for (int fm = 0; fm < 2; fm++) {
                        mma16816(accu[fm][fn], ah[fm], b1h);
                        mma16816(accu[fm][fn], ah[fm], b1l);
                        mma16816(accu[fm][fn], al[fm], b1h);
                    }
                }
            }
        }
        __syncthreads();
    }

    // epilogue
    #pragma unroll
    for (int fm = 0; fm < 2; fm++) {
        int rbase = m0 + wr*32 + fm*16 + (lane >> 2);
        #pragma unroll
        for (int half = 0; half < 2; half++) {
            int gm = rbase + half*8;
            if (AMODE != 0 && gm >= rows) continue;
            float w = 0.f;
            if (MODE == 2) w = g_lw[base + gm];
            #pragma unroll
            for (int fn = 0; fn < 4; fn++) {
                int col = n0 + wc*32 + fn*8 + (lane & 3)*2;
                float c0 = accg[fm][fn][half*2+0];
                float c1 = accg[fm][fn][half*2+1];
                if (MODE == 0) {
                    *(float2*)&C[(size_t)gm * ldc + col] = make_float2(c0, c1);
                } else if (MODE == 1) {
                    float u0 = accu[fm][fn][half*2+0];
                    float u1 = accu[fm][fn][half*2+1];
                    float s0 = c0 / (1.f + __expf(-c0)) * u0;
                    float s1 = c1 / (1.f + __expf(-c1)) * u1;
                    int rc = (AMODE != 0) ? (base + gm) : gm;
                    bf16 h0,l0,h1,l1;
                    split32(s0,h0,l0); split32(s1,h1,l1);
                    __nv_bfloat162 hh; hh.x = h0; hh.y = h1;
                    __nv_bfloat162 ll; ll.x = l0; ll.y = l1;
                    *(__nv_bfloat162*)&Ch[(size_t)rc * ldc + col] = hh;
                    *(__nv_bfloat162*)&Cl[(size_t)rc * ldc + col] = ll;
                } else { // MODE == 2: per-slot weighted store
                    int rc = base + gm;
                    *(float2*)&C[(size_t)rc * ldc + col] = make_float2(c0 * w, c1 * w);
                }
            }
        }
    }
}

// ---------------- final gather-reduce: out[t] += sum of 6 slot rows ----------------
__global__ void reduce_out(float* __restrict__ out) {
    int t = blockIdx.x;
    int p[TOPK];
    #pragma unroll
    for (int k = 0; k < TOPK; k++) p[k] = g_pos[t*TOPK + k];
    float4* o4 = (float4*)(out + (size_t)t * Hh);
    for (int c = threadIdx.x; c < Hh/4; c += blockDim.x) {
        float4 v = o4[c];
        #pragma unroll
        for (int k = 0; k < TOPK; k++) {
            float4 d = ((const float4*)(g_dout + (size_t)p[k] * Hh))[c];
            v.x += d.x; v.y += d.y; v.z += d.z; v.w += d.w;
        }
        o4[c] = v;
    }
}

// ---------------- launch ----------------
extern "C" void kernel_launch(void* const* d_in, const int* in_sizes, int n_in,
                              void* d_out, int out_size) {
    const float* x      = (const float*)d_in[0];
    const float* wr     = (const float*)d_in[1];
    const float* wgexp  = (const float*)d_in[2];
    const float* wuexp  = (const float*)d_in[3];
    const float* wdexp  = (const float*)d_in[4];
    const float* wsg    = (const float*)d_in[5];
    const float* wsu    = (const float*)d_in[6];
    const float* wsd    = (const float*)d_in[7];
    float* out = (float*)d_out;

    float *pLog, *pDout;
    bf16 *pWg_h,*pWg_l,*pWu_h,*pWu_l,*pWd_h,*pWd_l;
    bf16 *pSg_h,*pSg_l,*pSu_h,*pSu_l,*pSd_h,*pSd_l;
    bf16 *pXh,*pXl,*pShh,*pShl,*pAh,*pAl;
    cudaGetSymbolAddress((void**)&pLog, g_logits);
    cudaGetSymbolAddress((void**)&pDout, g_dout);
    cudaGetSymbolAddress((void**)&pWg_h, g_Wg_h); cudaGetSymbolAddress((void**)&pWg_l, g_Wg_l);
    cudaGetSymbolAddress((void**)&pWu_h, g_Wu_h); cudaGetSymbolAddress((void**)&pWu_l, g_Wu_l);
    cudaGetSymbolAddress((void**)&pWd_h, g_Wd_h); cudaGetSymbolAddress((void**)&pWd_l, g_Wd_l);
    cudaGetSymbolAddress((void**)&pSg_h, g_Sg_h); cudaGetSymbolAddress((void**)&pSg_l, g_Sg_l);
    cudaGetSymbolAddress((void**)&pSu_h, g_Su_h); cudaGetSymbolAddress((void**)&pSu_l, g_Su_l);
    cudaGetSymbolAddress((void**)&pSd_h, g_Sd_h); cudaGetSymbolAddress((void**)&pSd_l, g_Sd_l);
    cudaGetSymbolAddress((void**)&pXh, g_xh);   cudaGetSymbolAddress((void**)&pXl, g_xl);
    cudaGetSymbolAddress((void**)&pShh, g_shh); cudaGetSymbolAddress((void**)&pShl, g_shl);
    cudaGetSymbolAddress((void**)&pAh, g_acth); cudaGetSymbolAddress((void**)&pAl, g_actl);

    const int SMEM1 = (2*128*40 + 4*64*40) * 2 * 2;  // MODE=1: 81920 B
    const int SMEM0 = (2*128*40 + 2*64*40) * 2 * 2;  // MODE=0/2: 61440 B
    cudaFuncSetAttribute(mma2<1,0>, cudaFuncAttributeMaxDynamicSharedMemorySize, SMEM1);
    cudaFuncSetAttribute(mma2<1,1>, cudaFuncAttributeMaxDynamicSharedMemorySize, SMEM1);
    cudaFuncSetAttribute(mma2<0,0>, cudaFuncAttributeMaxDynamicSharedMemorySize, SMEM0);
    cudaFuncSetAttribute(mma2<2,2>, cudaFuncAttributeMaxDynamicSharedMemorySize, SMEM0);

    // 1) router (fp32)
    zero_cnt<<<1, 64>>>();
    router_gemm<<<BT/64, 256>>>(x, wr, pLog);
    router_topk<<<BT, 32>>>();
    scan_off<<<1, 32>>>();
    build_lists<<<NEXP, 256>>>();

    // 2) split x; repack + split weights
    split_copy<<<(BT*Hh/4 + 255)/256, 256>>>(x, pXh, pXl, BT*Hh/4);
    repack_gu_split<<<dim3(Hh/32, NEXP/32, Ee), dim3(32,32)>>>(wgexp, pWg_h, pWg_l);
    repack_gu_split<<<dim3(Hh/32, NEXP/32, Ee), dim3(32,32)>>>(wuexp, pWu_h, pWu_l);
    repack_dn_split<<<dim3(Ee/32, NEXP/32, Hh), dim3(32,32)>>>(wdexp, pWd_h, pWd_l);
    split_copy<<<(FFN*Hh/4 + 255)/256, 256>>>(wsg, pSg_h, pSg_l, FFN*Hh/4);
    split_copy<<<(FFN*Hh/4 + 255)/256, 256>>>(wsu, pSu_h, pSu_l, FFN*Hh/4);
    split_copy<<<(Hh*FFN/4 + 255)/256, 256>>>(wsd, pSd_h, pSd_l, Hh*FFN/4);

    // 3) up GEMMs (silu(g)*u, split-store bf16 hi/lo)
    mma2<1,0><<<dim3(BT/128, FFN/64), 256, SMEM1>>>(
        pXh, pXl, Hh, pSg_h, pSg_l, pSu_h, pSu_l, 0,
        nullptr, pShh, pShl, FFN, BT, Hh, 1);
    mma2<1,1><<<dim3(BT/128, NEXP*(Ee/64)), 256, SMEM1>>>(
        pXh, pXl, Hh, pWg_h, pWg_l, pWu_h, pWu_l, (size_t)Ee*Hh,
        nullptr, pAh, pAl, Ee, 0, Hh, Ee/64);

    // 4) down GEMMs
    mma2<0,0><<<dim3(BT/128, Hh/64), 256, SMEM0>>>(
        pShh, pShl, FFN, pSd_h, pSd_l, nullptr, nullptr, 0,
        out, nullptr, nullptr, Hh, BT, FFN, 1);
    mma2<2,2><<<dim3(BT/128, NEXP*(Hh/64)), 256, SMEM0>>>(
        pAh, pAl, Ee, pWd_h, pWd_l, nullptr, nullptr, (size_t)Hh*Ee,
        pDout, nullptr, nullptr, Hh, 0, Ee, Hh/64);

    // 5) combine routed + shared
    reduce_out<<<BT, 256>>>(out);
}